// round 16
// baseline (speedup 1.0000x reference)
#include <cuda_runtime.h>
#include <cuda_fp16.h>
#include <stdint.h>

#define HW 1024
#define CH 256
#define BS 32
#define NROWS 65536
#define MT 64
#define NBLK (NROWS/MT)

#define OFF_X   0                 // fp16 [64][264] (permuted cols)
#define OFF_A0  33792             // fp16 [64][264] ping
#define OFF_A1  67584             // fp16 [64][264] pong
#define OFF_RED 101376            // 64*32 f32
#define OFF_CW  109568            // 512 f32 (permuted)
#define OFF_LIN 111616            // 64 ints
#define SMEM_TOTAL 111872

__device__ float g_t[(size_t)BS*HW*CH];                       // [b][p][c]
__device__ __align__(16) unsigned char g_wb[(size_t)6*8*16384]; // frag-packed fp16 weights

// channel permutation (involution): logical <-> physical MMA column
__device__ __forceinline__ int chperm(int c){
    return (c&~31)|(((c>>1)&3)<<3)|(((c>>3)&3)<<1)|(c&1);
}

// ---------- helpers ----------
__device__ __forceinline__ uint32_t s2u(const void* p){
    uint32_t a; asm("{ .reg .u64 t; cvta.to.shared.u64 t, %1; cvt.u32.u64 %0, t; }":"=r"(a):"l"(p)); return a;
}
__device__ __forceinline__ uint32_t lds32(uint32_t a){
    uint32_t v; asm volatile("ld.shared.b32 %0,[%1];":"=r"(v):"r"(a)); return v;
}
__device__ __forceinline__ void sts32(uint32_t a,uint32_t v){
    asm volatile("st.shared.b32 [%0],%1;"::"r"(a),"r"(v));
}
__device__ __forceinline__ void sts128(uint32_t a,const uint32_t* v){
    asm volatile("st.shared.v4.b32 [%0],{%1,%2,%3,%4};"::"r"(a),"r"(v[0]),"r"(v[1]),"r"(v[2]),"r"(v[3]));
}
__device__ __forceinline__ void ldsm4(uint32_t addr,uint32_t* r){
    asm volatile("ldmatrix.sync.aligned.m8n8.x4.shared.b16 {%0,%1,%2,%3}, [%4];"
        : "=r"(r[0]),"=r"(r[1]),"=r"(r[2]),"=r"(r[3]) : "r"(addr));
}
__device__ __forceinline__ float silu(float x){ return __fdividef(x,1.f+__expf(-x)); }
__device__ __forceinline__ uint32_t packh2(float f0,float f1){
    __half2 h=__floats2half2_rn(f0,f1); return *(uint32_t*)&h;
}
__device__ __forceinline__ float2 unph2(uint32_t u){
    return __half22float2(*(__half2*)&u);
}
__device__ __forceinline__ void mma16816(float* d,const uint32_t* a,uint32_t b0,uint32_t b1){
    asm volatile("mma.sync.aligned.m16n8k16.row.col.f32.f16.f16.f32 "
        "{%0,%1,%2,%3}, {%4,%5,%6,%7}, {%8,%9}, {%0,%1,%2,%3};"
        : "+f"(d[0]),"+f"(d[1]),"+f"(d[2]),"+f"(d[3])
        : "r"(a[0]),"r"(a[1]),"r"(a[2]),"r"(a[3]),"r"(b0),"r"(b1));
}

// ---------- kernel 1: transpose [b][c][p] -> [b][p][c] ----------
__global__ void transpose_kernel(const float* __restrict__ g){
    __shared__ float tile[32][33];
    int b=blockIdx.z, p0=blockIdx.x*32, c0=blockIdx.y*32;
    int tx=threadIdx.x, ty=threadIdx.y;
    const float* src=g+(size_t)b*CH*HW;
    float* dst=g_t+(size_t)b*HW*CH;
#pragma unroll
    for(int i=0;i<4;i++) tile[ty+i*8][tx]=src[(size_t)(c0+ty+i*8)*HW+p0+tx];
    __syncthreads();
#pragma unroll
    for(int i=0;i<4;i++) dst[(size_t)(p0+ty+i*8)*CH+c0+tx]=tile[tx][ty+i*8];
}

// ---------- kernel 2: weights -> fp16 fragments, permuted n and k ----------
__global__ void prep_kernel(const float* __restrict__ c1,const float* __restrict__ c2,
                            const float* __restrict__ m1,const float* __restrict__ m2){
    int gid=blockIdx.x*256+threadIdx.x;          // 98304 total
    int lane=gid&31, nt=(gid>>5)&31, ks=(gid>>10)&1, kc=(gid>>11)&7, w=gid>>14;
    int q=lane&3, g=lane>>2;
    int nh=nt>>2, lt=nt&3;
    int n_l=chperm(nt*8+g);
    int k0=kc*32+ks*16+q*2;
    int kl0=chperm(k0), kl2=chperm(k0+8);
    float v0,v1,v2,v3;
    if(w<4){
        const float* s=(w&1)?c2:c1; int L=w>>1;
        const float* p=s+((size_t)(L*CH+n_l)*CH)*9+4;
        v0=p[(size_t)kl0*9]; v1=p[(size_t)(kl0+1)*9];
        v2=p[(size_t)kl2*9]; v3=p[(size_t)(kl2+1)*9];
    } else {
        const float* p=((w==4)?m1:m2)+(size_t)n_l*CH;
        v0=p[kl0]; v1=p[kl0+1]; v2=p[kl2]; v3=p[kl2+1];
    }
    size_t base=(size_t)(w*8+kc)*16384;
    uint32_t fo=(uint32_t)(ks*8192+nh*1024+lane*32+lt*8);
    *(uint2*)(g_wb+base+fo)=make_uint2(packh2(v0,v1),packh2(v2,v3));
}

// ---------- GEMM: D[64][256] = A[64][256] x W^T; B LDG.128 depth-3 ----------
__device__ __forceinline__ void run_gemm(int w,uint32_t smb,uint32_t aoff,int nh,int lane,
                                         float d[16][4]){
#pragma unroll
    for(int i=0;i<16;i++){d[i][0]=0.f;d[i][1]=0.f;d[i][2]=0.f;d[i][3]=0.f;}
    const unsigned char* wb=g_wb+(size_t)w*131072;
    uint32_t lo=((uint32_t)nh<<10)+((uint32_t)lane<<5);
    uint32_t abase=smb+aoff+(uint32_t)(lane&15)*528+((lane&16)?16u:0u);
    uint4 bp[3][2];
#pragma unroll
    for(int s=0;s<3;s++){
        const unsigned char* src=wb+(s>>1)*16384+(s&1)*8192+lo;
        bp[s][0]=__ldg((const uint4*)(src));
        bp[s][1]=__ldg((const uint4*)(src+16));
    }
#pragma unroll
    for(int kst=0;kst<16;kst++){
        uint4 b01=bp[kst%3][0], b23=bp[kst%3][1];
        if(kst<13){
            int kn=kst+3;
            const unsigned char* src=wb+(kn>>1)*16384+(kn&1)*8192+lo;
            bp[kst%3][0]=__ldg((const uint4*)(src));
            bp[kst%3][1]=__ldg((const uint4*)(src+16));
        }
        uint32_t ak=abase+(uint32_t)kst*32;
        uint32_t ah[4][4];
#pragma unroll
        for(int mf=0;mf<4;mf++) ldsm4(ak+(uint32_t)mf*(16*528),ah[mf]);
#pragma unroll
        for(int mf=0;mf<4;mf++){
            mma16816(d[mf*4+0],ah[mf],b01.x,b01.y);
            mma16816(d[mf*4+1],ah[mf],b01.z,b01.w);
            mma16816(d[mf*4+2],ah[mf],b23.x,b23.y);
            mma16816(d[mf*4+3],ah[mf],b23.z,b23.w);
        }
    }
}

// thread-local GN+SiLU over the 8 cols (one group) a quad-lane owns, one row
#define GN8(MF,I0,GW,GB,LB) { \
    float s_=0.f; \
    _Pragma("unroll") for(int lt_=0;lt_<4;lt_++) s_+=d[(MF)*4+lt_][I0]+d[(MF)*4+lt_][(I0)+1]; \
    float mn_=s_*0.125f, vv_=0.f; \
    _Pragma("unroll") for(int lt_=0;lt_<4;lt_++){ \
        float e0_=d[(MF)*4+lt_][I0]-mn_, e1_=d[(MF)*4+lt_][(I0)+1]-mn_; vv_+=e0_*e0_+e1_*e1_; } \
    float rs_=rsqrtf(vv_*0.125f+1e-5f); \
    _Pragma("unroll") for(int lt_=0;lt_<4;lt_++){ \
        int l_=(LB)+lt_*2; \
        d[(MF)*4+lt_][I0]    =silu((d[(MF)*4+lt_][I0]    -mn_)*rs_*(GW)[l_]  +(GB)[l_]); \
        d[(MF)*4+lt_][(I0)+1]=silu((d[(MF)*4+lt_][(I0)+1]-mn_)*rs_*(GW)[l_+1]+(GB)[l_+1]); } }

// ---------- fused main kernel ----------
__global__ __launch_bounds__(256,2) void main_kernel(
    const int* __restrict__ pts,
    const float* __restrict__ gn1w,const float* __restrict__ gn1b,
    const float* __restrict__ c1b,
    const float* __restrict__ gn2w,const float* __restrict__ gn2b,
    const float* __restrict__ c2b,
    const float* __restrict__ clsw,const float* __restrict__ clsb,
    const float* __restrict__ mb1,const float* __restrict__ mb2,
    const float* __restrict__ mw3,const float* __restrict__ mb3,
    float* __restrict__ out)
{
    extern __shared__ __align__(16) unsigned char smp[];
    uint32_t smb=s2u(smp);
    int tid=threadIdx.x, lane=tid&31, nh=tid>>5;
    int g=lane>>2, q=lane&3;
    int row_base=blockIdx.x*MT;
    float* cws=(float*)(smp+OFF_CW);
    float* red=(float*)(smp+OFF_RED);

    for(int i=tid;i<512;i+=256)  cws[i]=clsw[(i&~255)+chperm(i&255)];
    if(tid<MT){
        int r=row_base+tid;
        int p0=pts[r*2], p1=pts[r*2+1];
        ((int*)(smp+OFF_LIN))[tid]=((r>>11)*HW+((p0>>3)*32+(p1>>3)))*CH;
    }
    __syncthreads();

    // gather -> X(fp16, permuted) ; GN1[0]+SiLU -> A0(fp16, permuted)
    {
        int row=tid>>2, t4=tid&3;
        const float* src=g_t+((const int*)(smp+OFF_LIN))[row]+t4*64;
        float v[64];
#pragma unroll
        for(int i=0;i<16;i++) *(float4*)(v+i*4)=*(const float4*)(src+i*4);
        uint32_t tmp[32];
#pragma unroll
        for(int p2=0;p2<32;p2++){
            int l=chperm(t4*64+p2*2)-t4*64;
            tmp[p2]=packh2(v[l],v[l+1]);
        }
        uint32_t xrb=smb+OFF_X+row*528+t4*128;
#pragma unroll
        for(int i=0;i<8;i++) sts128(xrb+i*16,tmp+i*4);
#pragma unroll
        for(int gr=0;gr<8;gr++){
            float s=0.f,vv=0.f;
#pragma unroll
            for(int j=0;j<8;j++) s+=v[gr*8+j];
            float mean=s*0.125f;
#pragma unroll
            for(int j=0;j<8;j++){float e=v[gr*8+j]-mean; vv+=e*e;}
            float rs=rsqrtf(vv*0.125f+1e-5f);
#pragma unroll
            for(int j=0;j<8;j++){
                int n=t4*64+gr*8+j;
                v[gr*8+j]=silu((v[gr*8+j]-mean)*rs*gn1w[n]+gn1b[n]);
            }
        }
#pragma unroll
        for(int p2=0;p2<32;p2++){
            int l=chperm(t4*64+p2*2)-t4*64;
            tmp[p2]=packh2(v[l],v[l+1]);
        }
        uint32_t arb=smb+OFF_A0+row*528+t4*128;
#pragma unroll
        for(int i=0;i<8;i++) sts128(arb+i*16,tmp+i*4);
    }
    __syncthreads();

    float d[16][4];
    int lb=nh*32+q*8;   // logical channel base for this quad lane
    uint32_t cur=OFF_A0, nxt=OFF_A1;

#pragma unroll 1
    for(int L=0;L<2;++L){
        run_gemm(L*2+0,smb,cur,nh,lane,d);                 // conv1 (reads cur)
        {
            const float* b1=c1b+L*CH; const float* g2w=gn2w+L*CH; const float* g2b=gn2b+L*CH;
#pragma unroll
            for(int mf=0;mf<4;mf++){
#pragma unroll
                for(int lt=0;lt<4;lt++){
                    float bb0=b1[lb+lt*2], bb1=b1[lb+lt*2+1];
                    d[mf*4+lt][0]+=bb0; d[mf*4+lt][1]+=bb1;
                    d[mf*4+lt][2]+=bb0; d[mf*4+lt][3]+=bb1;
                }
                GN8(mf,0,g2w,g2b,lb);
                GN8(mf,2,g2w,g2b,lb);
#pragma unroll
                for(int lt=0;lt<4;lt++){
                    uint32_t ro=(uint32_t)(mf*16+g)*528+(uint32_t)(nh*32+lt*8+q*2)*2;
                    sts32(smb+nxt+ro,packh2(d[mf*4+lt][0],d[mf*4+lt][1]));
                    sts32(smb+nxt+ro+8*528,packh2(d[mf*4+lt][2],d[mf*4+lt][3]));
                }
            }
        }
        __syncthreads();
        { uint32_t t=cur; cur=nxt; nxt=t; }

        run_gemm(L*2+1,smb,cur,nh,lane,d);                 // conv2 (reads cur)
        {
            const float* b2=c2b+L*CH; const float* g1w=gn1w+CH; const float* g1b=gn1b+CH;
#pragma unroll
            for(int mf=0;mf<4;mf++){
#pragma unroll
                for(int lt=0;lt<4;lt++){
                    uint32_t ro=(uint32_t)(mf*16+g)*528+(uint32_t)(nh*32+lt*8+q*2)*2;
                    float bb0=b2[lb+lt*2], bb1=b2[lb+lt*2+1];
                    float2 xf=unph2(lds32(smb+OFF_X+ro));
                    d[mf*4+lt][0]+=bb0+xf.x; d[mf*4+lt][1]+=bb1+xf.y;
                    sts32(smb+OFF_X+ro,packh2(d[mf*4+lt][0],d[mf*4+lt][1]));
                    xf=unph2(lds32(smb+OFF_X+ro+8*528));
                    d[mf*4+lt][2]+=bb0+xf.x; d[mf*4+lt][3]+=bb1+xf.y;
                    sts32(smb+OFF_X+ro+8*528,packh2(d[mf*4+lt][2],d[mf*4+lt][3]));
                }
                if(L==0){ GN8(mf,0,g1w,g1b,lb); GN8(mf,2,g1w,g1b,lb); }
#pragma unroll
                for(int lt=0;lt<4;lt++){
                    uint32_t ro=(uint32_t)(mf*16+g)*528+(uint32_t)(nh*32+lt*8+q*2)*2;
                    sts32(smb+nxt+ro,packh2(d[mf*4+lt][0],d[mf*4+lt][1]));
                    sts32(smb+nxt+ro+8*528,packh2(d[mf*4+lt][2],d[mf*4+lt][3]));
                }
            }
        }
        __syncthreads();
        { uint32_t t=cur; cur=nxt; nxt=t; }
    }

    run_gemm(4,smb,cur,nh,lane,d);                         // mlp1 (reads cur)
#pragma unroll
    for(int e=0;e<16;e++){
        int mf=e>>2, lt=e&3;
        float bb0=mb1[lb+lt*2], bb1=mb1[lb+lt*2+1];
        uint32_t ro=(uint32_t)(mf*16+g)*528+(uint32_t)(nh*32+lt*8+q*2)*2;
        d[e][0]=fmaxf(d[e][0]+bb0,0.f);   d[e][1]=fmaxf(d[e][1]+bb1,0.f);
        d[e][2]=fmaxf(d[e][2]+bb0,0.f);   d[e][3]=fmaxf(d[e][3]+bb1,0.f);
        sts32(smb+nxt+ro,packh2(d[e][0],d[e][1]));
        sts32(smb+nxt+ro+8*528,packh2(d[e][2],d[e][3]));
    }
    __syncthreads();
    { uint32_t t=cur; cur=nxt; nxt=t; }

    run_gemm(5,smb,cur,nh,lane,d);                         // mlp2 (reads cur)
    {
        float bxa[4][4], bxb[4][4];
#pragma unroll
        for(int mf=0;mf<4;mf++)
#pragma unroll
            for(int s=0;s<4;s++){ bxa[mf][s]=0.f; bxb[mf][s]=0.f; }
#pragma unroll
        for(int e=0;e<16;e++){
            int mf=e>>2, lt=e&3;
            float bb0=mb2[lb+lt*2], bb1=mb2[lb+lt*2+1];
            float t0=fmaxf(d[e][0]+bb0,0.f),  t1=fmaxf(d[e][1]+bb1,0.f);
            float t2=fmaxf(d[e][2]+bb0,0.f),  t3=fmaxf(d[e][3]+bb1,0.f);
#pragma unroll
            for(int s=0;s<4;s++){
                float w0=__ldg(mw3+s*256+lb+lt*2), w1=__ldg(mw3+s*256+lb+lt*2+1);
                bxa[mf][s]+=t0*w0+t1*w1;
                bxb[mf][s]+=t2*w0+t3*w1;
            }
        }
#pragma unroll
        for(int mf=0;mf<4;mf++)
#pragma unroll
            for(int s=0;s<4;s++){
                bxa[mf][s]+=__shfl_xor_sync(0xffffffffu,bxa[mf][s],1);
                bxa[mf][s]+=__shfl_xor_sync(0xffffffffu,bxa[mf][s],2);
                bxb[mf][s]+=__shfl_xor_sync(0xffffffffu,bxb[mf][s],1);
                bxb[mf][s]+=__shfl_xor_sync(0xffffffffu,bxb[mf][s],2);
            }
        if(q==0){
#pragma unroll
            for(int mf=0;mf<4;mf++)
#pragma unroll
                for(int s=0;s<4;s++){
                    red[(mf*16+g)*32+nh*4+s]=bxa[mf][s];
                    red[(mf*16+g+8)*32+nh*4+s]=bxb[mf][s];
                }
        }
    }
    __syncthreads();

    // heads out
    if(tid<MT){
        size_t row=(size_t)row_base+tid;
#pragma unroll
        for(int s=0;s<4;s++){
            float a=mb3[s];
#pragma unroll
            for(int h=0;h<8;h++) a+=red[tid*32+h*4+s];
            out[131072+row*4+s]=__fdividef(1.f,1.f+__expf(-a));
        }
    }
    {
        int row=tid>>2, t4=tid&3;
        uint32_t xbb=smb+OFF_X+row*528+t4*128;
        float c0=0.f,c1=0.f;
#pragma unroll 8
        for(int j=0;j<32;j++){
            float2 xf=unph2(lds32(xbb+j*4));
            int k=t4*64+j*2;
            c0+=xf.x*cws[k]+xf.y*cws[k+1];
            c1+=xf.x*cws[256+k]+xf.y*cws[256+k+1];
        }
        c0+=__shfl_xor_sync(0xffffffffu,c0,1); c0+=__shfl_xor_sync(0xffffffffu,c0,2);
        c1+=__shfl_xor_sync(0xffffffffu,c1,1); c1+=__shfl_xor_sync(0xffffffffu,c1,2);
        if(t4==0){
            size_t r=(size_t)row_base+row;
            out[r*2+0]=c0+clsb[0];
            out[r*2+1]=c1+clsb[1];
        }
    }
}

// ---------- launch ----------
extern "C" void kernel_launch(void* const* d_in, const int* in_sizes, int n_in,
                              void* d_out, int out_size){
    const float* gimage=(const float*)d_in[0];
    const int*   pts   =(const int*)  d_in[1];
    const float* gn1w=(const float*)d_in[2],  *gn1b=(const float*)d_in[3];
    const float* c1w =(const float*)d_in[4],  *c1b =(const float*)d_in[5];
    const float* gn2w=(const float*)d_in[6],  *gn2b=(const float*)d_in[7];
    const float* c2w =(const float*)d_in[8],  *c2b =(const float*)d_in[9];
    const float* clsw=(const float*)d_in[10], *clsb=(const float*)d_in[11];
    const float* mw1 =(const float*)d_in[12], *mb1 =(const float*)d_in[13];
    const float* mw2 =(const float*)d_in[14], *mb2 =(const float*)d_in[15];
    const float* mw3 =(const float*)d_in[16], *mb3 =(const float*)d_in[17];
    float* out=(float*)d_out;

    cudaFuncSetAttribute(main_kernel, cudaFuncAttributeMaxDynamicSharedMemorySize, SMEM_TOTAL);

    dim3 tgrid(HW/32, CH/32, BS), tblk(32,8);
    transpose_kernel<<<tgrid,tblk>>>(gimage);
    prep_kernel<<<384,256>>>(c1w,c2w,mw1,mw2);
    main_kernel<<<NBLK,256,SMEM_TOTAL>>>(pts,gn1w,gn1b,c1b,gn2w,gn2b,c2b,
                                         clsw,clsb,mb1,mb2,mw3,mb3,out);
}

// round 17
// speedup vs baseline: 1.0628x; 1.0628x over previous
#include <cuda_runtime.h>
#include <cuda_fp16.h>
#include <stdint.h>

#define HW 1024
#define CH 256
#define BS 32
#define NROWS 65536
#define MT 64
#define NBLK (NROWS/MT)

#define OFF_X   0                 // fp16 [64][264] (permuted cols)
#define OFF_A   33792             // fp16 [64][264] (permuted cols)
#define OFF_RED 33792             // overlays A (A dead after gemm5)
#define OFF_W3  67584             // 1024 f32 (permuted)
#define OFF_CW  71680             // 512 f32 (permuted)
#define OFF_LIN 73728             // 64 ints
#define SMEM_TOTAL 73984

__device__ __half g_t[(size_t)BS*HW*CH];                      // [b][p][c] fp16
__device__ __align__(16) unsigned char g_wb[(size_t)6*8*16384]; // frag-packed fp16 weights

// channel permutation (involution): logical <-> physical MMA column
__device__ __forceinline__ int chperm(int c){
    return (c&~31)|(((c>>1)&3)<<3)|(((c>>3)&3)<<1)|(c&1);
}

// ---------- helpers ----------
__device__ __forceinline__ uint32_t s2u(const void* p){
    uint32_t a; asm("{ .reg .u64 t; cvta.to.shared.u64 t, %1; cvt.u32.u64 %0, t; }":"=r"(a):"l"(p)); return a;
}
__device__ __forceinline__ uint32_t lds32(uint32_t a){
    uint32_t v; asm volatile("ld.shared.b32 %0,[%1];":"=r"(v):"r"(a)); return v;
}
__device__ __forceinline__ void sts32(uint32_t a,uint32_t v){
    asm volatile("st.shared.b32 [%0],%1;"::"r"(a),"r"(v));
}
__device__ __forceinline__ void sts128(uint32_t a,const uint32_t* v){
    asm volatile("st.shared.v4.b32 [%0],{%1,%2,%3,%4};"::"r"(a),"r"(v[0]),"r"(v[1]),"r"(v[2]),"r"(v[3]));
}
__device__ __forceinline__ void ldsm4(uint32_t addr,uint32_t* r){
    asm volatile("ldmatrix.sync.aligned.m8n8.x4.shared.b16 {%0,%1,%2,%3}, [%4];"
        : "=r"(r[0]),"=r"(r[1]),"=r"(r[2]),"=r"(r[3]) : "r"(addr));
}
__device__ __forceinline__ float silu(float x){ return __fdividef(x,1.f+__expf(-x)); }
__device__ __forceinline__ uint32_t packh2(float f0,float f1){
    __half2 h=__floats2half2_rn(f0,f1); return *(uint32_t*)&h;
}
__device__ __forceinline__ float2 unph2(uint32_t u){
    return __half22float2(*(__half2*)&u);
}
__device__ __forceinline__ void mma16816(float* d,const uint32_t* a,uint32_t b0,uint32_t b1){
    asm volatile("mma.sync.aligned.m16n8k16.row.col.f32.f16.f16.f32 "
        "{%0,%1,%2,%3}, {%4,%5,%6,%7}, {%8,%9}, {%0,%1,%2,%3};"
        : "+f"(d[0]),"+f"(d[1]),"+f"(d[2]),"+f"(d[3])
        : "r"(a[0]),"r"(a[1]),"r"(a[2]),"r"(a[3]),"r"(b0),"r"(b1));
}

// ---------- kernel 1: transpose [b][c][p] -> [b][p][c] (fp32 -> fp16) -------
__global__ void transpose_kernel(const float* __restrict__ g){
    __shared__ float tile[32][33];
    int b=blockIdx.z, p0=blockIdx.x*32, c0=blockIdx.y*32;
    int tx=threadIdx.x, ty=threadIdx.y;
    const float* src=g+(size_t)b*CH*HW;
    __half* dst=g_t+(size_t)b*HW*CH;
#pragma unroll
    for(int i=0;i<4;i++) tile[ty+i*8][tx]=src[(size_t)(c0+ty+i*8)*HW+p0+tx];
    __syncthreads();
#pragma unroll
    for(int i=0;i<4;i++) dst[(size_t)(p0+ty+i*8)*CH+c0+tx]=__float2half_rn(tile[tx][ty+i*8]);
}

// ---------- kernel 2: weights -> fp16 fragments, permuted n and k ----------
__global__ void prep_kernel(const float* __restrict__ c1,const float* __restrict__ c2,
                            const float* __restrict__ m1,const float* __restrict__ m2){
    int gid=blockIdx.x*256+threadIdx.x;          // 98304 total
    int lane=gid&31, nt=(gid>>5)&31, ks=(gid>>10)&1, kc=(gid>>11)&7, w=gid>>14;
    int q=lane&3, g=lane>>2;
    int nh=nt>>2, lt=nt&3;
    int n_l=chperm(nt*8+g);
    int k0=kc*32+ks*16+q*2;
    int kl0=chperm(k0), kl2=chperm(k0+8);
    float v0,v1,v2,v3;
    if(w<4){
        const float* s=(w&1)?c2:c1; int L=w>>1;
        const float* p=s+((size_t)(L*CH+n_l)*CH)*9+4;
        v0=p[(size_t)kl0*9]; v1=p[(size_t)(kl0+1)*9];
        v2=p[(size_t)kl2*9]; v3=p[(size_t)(kl2+1)*9];
    } else {
        const float* p=((w==4)?m1:m2)+(size_t)n_l*CH;
        v0=p[kl0]; v1=p[kl0+1]; v2=p[kl2]; v3=p[kl2+1];
    }
    size_t base=(size_t)(w*8+kc)*16384;
    uint32_t fo=(uint32_t)(ks*8192+nh*1024+lane*32+lt*8);
    *(uint2*)(g_wb+base+fo)=make_uint2(packh2(v0,v1),packh2(v2,v3));
}

// ---------- GEMM: D[64][256] = A[64][256] x W^T; B LDG.128 depth-3 ----------
__device__ __forceinline__ void run_gemm(int w,uint32_t smb,int nh,int lane,
                                         float d[16][4]){
#pragma unroll
    for(int i=0;i<16;i++){d[i][0]=0.f;d[i][1]=0.f;d[i][2]=0.f;d[i][3]=0.f;}
    const unsigned char* wb=g_wb+(size_t)w*131072;
    uint32_t lo=((uint32_t)nh<<10)+((uint32_t)lane<<5);
    uint32_t abase=smb+OFF_A+(uint32_t)(lane&15)*528+((lane&16)?16u:0u);
    uint4 bp[3][2];
#pragma unroll
    for(int s=0;s<3;s++){
        const unsigned char* src=wb+(s>>1)*16384+(s&1)*8192+lo;
        bp[s][0]=__ldg((const uint4*)(src));
        bp[s][1]=__ldg((const uint4*)(src+16));
    }
#pragma unroll
    for(int kst=0;kst<16;kst++){
        uint4 b01=bp[kst%3][0], b23=bp[kst%3][1];
        if(kst<13){
            int kn=kst+3;
            const unsigned char* src=wb+(kn>>1)*16384+(kn&1)*8192+lo;
            bp[kst%3][0]=__ldg((const uint4*)(src));
            bp[kst%3][1]=__ldg((const uint4*)(src+16));
        }
        uint32_t ak=abase+(uint32_t)kst*32;
        uint32_t ah[4][4];
#pragma unroll
        for(int mf=0;mf<4;mf++) ldsm4(ak+(uint32_t)mf*(16*528),ah[mf]);
#pragma unroll
        for(int mf=0;mf<4;mf++){
            mma16816(d[mf*4+0],ah[mf],b01.x,b01.y);
            mma16816(d[mf*4+1],ah[mf],b01.z,b01.w);
            mma16816(d[mf*4+2],ah[mf],b23.x,b23.y);
            mma16816(d[mf*4+3],ah[mf],b23.z,b23.w);
        }
    }
}

// thread-local GN+SiLU over the 8 cols (one group) a quad-lane owns, one row
#define GN8(MF,I0,GW,GB,LB) { \
    float s_=0.f; \
    _Pragma("unroll") for(int lt_=0;lt_<4;lt_++) s_+=d[(MF)*4+lt_][I0]+d[(MF)*4+lt_][(I0)+1]; \
    float mn_=s_*0.125f, vv_=0.f; \
    _Pragma("unroll") for(int lt_=0;lt_<4;lt_++){ \
        float e0_=d[(MF)*4+lt_][I0]-mn_, e1_=d[(MF)*4+lt_][(I0)+1]-mn_; vv_+=e0_*e0_+e1_*e1_; } \
    float rs_=rsqrtf(vv_*0.125f+1e-5f); \
    _Pragma("unroll") for(int lt_=0;lt_<4;lt_++){ \
        int l_=(LB)+lt_*2; \
        d[(MF)*4+lt_][I0]    =silu((d[(MF)*4+lt_][I0]    -mn_)*rs_*(GW)[l_]  +(GB)[l_]); \
        d[(MF)*4+lt_][(I0)+1]=silu((d[(MF)*4+lt_][(I0)+1]-mn_)*rs_*(GW)[l_+1]+(GB)[l_+1]); } }

// ---------- fused main kernel ----------
__global__ __launch_bounds__(256,2) void main_kernel(
    const int* __restrict__ pts,
    const float* __restrict__ gn1w,const float* __restrict__ gn1b,
    const float* __restrict__ c1b,
    const float* __restrict__ gn2w,const float* __restrict__ gn2b,
    const float* __restrict__ c2b,
    const float* __restrict__ clsw,const float* __restrict__ clsb,
    const float* __restrict__ mb1,const float* __restrict__ mb2,
    const float* __restrict__ mw3,const float* __restrict__ mb3,
    float* __restrict__ out)
{
    extern __shared__ __align__(16) unsigned char smp[];
    uint32_t smb=s2u(smp);
    int tid=threadIdx.x, lane=tid&31, nh=tid>>5;
    int g=lane>>2, q=lane&3;
    int row_base=blockIdx.x*MT;
    float* w3s=(float*)(smp+OFF_W3);
    float* cws=(float*)(smp+OFF_CW);
    float* red=(float*)(smp+OFF_RED);

    for(int i=tid;i<1024;i+=256) w3s[i]=mw3[(i&~255)+chperm(i&255)];
    for(int i=tid;i<512;i+=256)  cws[i]=clsw[(i&~255)+chperm(i&255)];
    if(tid<MT){
        int r=row_base+tid;
        int p0=pts[r*2], p1=pts[r*2+1];
        ((int*)(smp+OFF_LIN))[tid]=((r>>11)*HW+((p0>>3)*32+(p1>>3)))*CH;
    }
    __syncthreads();

    // gather(fp16) -> X(fp16, permuted) ; GN1[0]+SiLU -> A(fp16, permuted)
    {
        int row=tid>>2, t4=tid&3;
        const __half* src=g_t+((const int*)(smp+OFF_LIN))[row]+t4*64;
        uint4 raw[8];
#pragma unroll
        for(int i=0;i<8;i++) raw[i]=*(const uint4*)(src+i*8);
        float v[64];
#pragma unroll
        for(int i=0;i<8;i++){
            const uint32_t* rw=(const uint32_t*)&raw[i];
#pragma unroll
            for(int j=0;j<4;j++){
                float2 f=unph2(rw[j]);
                v[i*8+j*2]=f.x; v[i*8+j*2+1]=f.y;
            }
        }
        uint32_t tmp[32];
#pragma unroll
        for(int p2=0;p2<32;p2++){
            int l=chperm(t4*64+p2*2)-t4*64;
            tmp[p2]=packh2(v[l],v[l+1]);
        }
        uint32_t xrb=smb+OFF_X+row*528+t4*128;
#pragma unroll
        for(int i=0;i<8;i++) sts128(xrb+i*16,tmp+i*4);
#pragma unroll
        for(int gr=0;gr<8;gr++){
            float s=0.f,vv=0.f;
#pragma unroll
            for(int j=0;j<8;j++) s+=v[gr*8+j];
            float mean=s*0.125f;
#pragma unroll
            for(int j=0;j<8;j++){float e=v[gr*8+j]-mean; vv+=e*e;}
            float rs=rsqrtf(vv*0.125f+1e-5f);
#pragma unroll
            for(int j=0;j<8;j++){
                int n=t4*64+gr*8+j;
                v[gr*8+j]=silu((v[gr*8+j]-mean)*rs*gn1w[n]+gn1b[n]);
            }
        }
#pragma unroll
        for(int p2=0;p2<32;p2++){
            int l=chperm(t4*64+p2*2)-t4*64;
            tmp[p2]=packh2(v[l],v[l+1]);
        }
        uint32_t arb=smb+OFF_A+row*528+t4*128;
#pragma unroll
        for(int i=0;i<8;i++) sts128(arb+i*16,tmp+i*4);
    }
    __syncthreads();

    float d[16][4];
    int lb=nh*32+q*8;   // logical channel base for this quad lane

#pragma unroll 1
    for(int L=0;L<2;++L){
        run_gemm(L*2+0,smb,nh,lane,d);                     // conv1
        __syncthreads();
        {
            const float* b1=c1b+L*CH; const float* g2w=gn2w+L*CH; const float* g2b=gn2b+L*CH;
#pragma unroll
            for(int mf=0;mf<4;mf++){
#pragma unroll
                for(int lt=0;lt<4;lt++){
                    float bb0=b1[lb+lt*2], bb1=b1[lb+lt*2+1];
                    d[mf*4+lt][0]+=bb0; d[mf*4+lt][1]+=bb1;
                    d[mf*4+lt][2]+=bb0; d[mf*4+lt][3]+=bb1;
                }
                GN8(mf,0,g2w,g2b,lb);
                GN8(mf,2,g2w,g2b,lb);
#pragma unroll
                for(int lt=0;lt<4;lt++){
                    uint32_t ro=(uint32_t)(mf*16+g)*528+(uint32_t)(nh*32+lt*8+q*2)*2;
                    sts32(smb+OFF_A+ro,packh2(d[mf*4+lt][0],d[mf*4+lt][1]));
                    sts32(smb+OFF_A+ro+8*528,packh2(d[mf*4+lt][2],d[mf*4+lt][3]));
                }
            }
        }
        __syncthreads();

        run_gemm(L*2+1,smb,nh,lane,d);                     // conv2
        __syncthreads();
        {
            const float* b2=c2b+L*CH; const float* g1w=gn1w+CH; const float* g1b=gn1b+CH;
#pragma unroll
            for(int mf=0;mf<4;mf++){
#pragma unroll
                for(int lt=0;lt<4;lt++){
                    uint32_t ro=(uint32_t)(mf*16+g)*528+(uint32_t)(nh*32+lt*8+q*2)*2;
                    float bb0=b2[lb+lt*2], bb1=b2[lb+lt*2+1];
                    float2 xf=unph2(lds32(smb+OFF_X+ro));
                    d[mf*4+lt][0]+=bb0+xf.x; d[mf*4+lt][1]+=bb1+xf.y;
                    sts32(smb+OFF_X+ro,packh2(d[mf*4+lt][0],d[mf*4+lt][1]));
                    xf=unph2(lds32(smb+OFF_X+ro+8*528));
                    d[mf*4+lt][2]+=bb0+xf.x; d[mf*4+lt][3]+=bb1+xf.y;
                    sts32(smb+OFF_X+ro+8*528,packh2(d[mf*4+lt][2],d[mf*4+lt][3]));
                }
                if(L==0){ GN8(mf,0,g1w,g1b,lb); GN8(mf,2,g1w,g1b,lb); }
#pragma unroll
                for(int lt=0;lt<4;lt++){
                    uint32_t ro=(uint32_t)(mf*16+g)*528+(uint32_t)(nh*32+lt*8+q*2)*2;
                    sts32(smb+OFF_A+ro,packh2(d[mf*4+lt][0],d[mf*4+lt][1]));
                    sts32(smb+OFF_A+ro+8*528,packh2(d[mf*4+lt][2],d[mf*4+lt][3]));
                }
            }
        }
        __syncthreads();
    }

    run_gemm(4,smb,nh,lane,d);                             // mlp1
    __syncthreads();
#pragma unroll
    for(int e=0;e<16;e++){
        int mf=e>>2, lt=e&3;
        float bb0=mb1[lb+lt*2], bb1=mb1[lb+lt*2+1];
        uint32_t ro=(uint32_t)(mf*16+g)*528+(uint32_t)(nh*32+lt*8+q*2)*2;
        d[e][0]=fmaxf(d[e][0]+bb0,0.f);   d[e][1]=fmaxf(d[e][1]+bb1,0.f);
        d[e][2]=fmaxf(d[e][2]+bb0,0.f);   d[e][3]=fmaxf(d[e][3]+bb1,0.f);
        sts32(smb+OFF_A+ro,packh2(d[e][0],d[e][1]));
        sts32(smb+OFF_A+ro+8*528,packh2(d[e][2],d[e][3]));
    }
    __syncthreads();

    run_gemm(5,smb,nh,lane,d);                             // mlp2
    __syncthreads();                                       // A dead after this; RED overlays A
    {
        float bxa[4][4], bxb[4][4];
#pragma unroll
        for(int mf=0;mf<4;mf++)
#pragma unroll
            for(int s=0;s<4;s++){ bxa[mf][s]=0.f; bxb[mf][s]=0.f; }
#pragma unroll
        for(int e=0;e<16;e++){
            int mf=e>>2, lt=e&3;
            int n0=nh*32+lt*8+q*2;
            float bb0=mb2[lb+lt*2], bb1=mb2[lb+lt*2+1];
            float t0=fmaxf(d[e][0]+bb0,0.f),  t1=fmaxf(d[e][1]+bb1,0.f);
            float t2=fmaxf(d[e][2]+bb0,0.f),  t3=fmaxf(d[e][3]+bb1,0.f);
#pragma unroll
            for(int s=0;s<4;s++){
                float w0=w3s[s*256+n0], w1=w3s[s*256+n0+1];
                bxa[mf][s]+=t0*w0+t1*w1;
                bxb[mf][s]+=t2*w0+t3*w1;
            }
        }
#pragma unroll
        for(int mf=0;mf<4;mf++)
#pragma unroll
            for(int s=0;s<4;s++){
                bxa[mf][s]+=__shfl_xor_sync(0xffffffffu,bxa[mf][s],1);
                bxa[mf][s]+=__shfl_xor_sync(0xffffffffu,bxa[mf][s],2);
                bxb[mf][s]+=__shfl_xor_sync(0xffffffffu,bxb[mf][s],1);
                bxb[mf][s]+=__shfl_xor_sync(0xffffffffu,bxb[mf][s],2);
            }
        if(q==0){
#pragma unroll
            for(int mf=0;mf<4;mf++)
#pragma unroll
                for(int s=0;s<4;s++){
                    red[(mf*16+g)*32+nh*4+s]=bxa[mf][s];
                    red[(mf*16+g+8)*32+nh*4+s]=bxb[mf][s];
                }
        }
    }
    __syncthreads();

    // heads out
    if(tid<MT){
        size_t row=(size_t)row_base+tid;
#pragma unroll
        for(int s=0;s<4;s++){
            float a=mb3[s];
#pragma unroll
            for(int h=0;h<8;h++) a+=red[tid*32+h*4+s];
            out[131072+row*4+s]=__fdividef(1.f,1.f+__expf(-a));
        }
    }
    {
        int row=tid>>2, t4=tid&3;
        uint32_t xbb=smb+OFF_X+row*528+t4*128;
        float c0=0.f,c1=0.f;
#pragma unroll 8
        for(int j=0;j<32;j++){
            float2 xf=unph2(lds32(xbb+j*4));
            int k=t4*64+j*2;
            c0+=xf.x*cws[k]+xf.y*cws[k+1];
            c1+=xf.x*cws[256+k]+xf.y*cws[256+k+1];
        }
        c0+=__shfl_xor_sync(0xffffffffu,c0,1); c0+=__shfl_xor_sync(0xffffffffu,c0,2);
        c1+=__shfl_xor_sync(0xffffffffu,c1,1); c1+=__shfl_xor_sync(0xffffffffu,c1,2);
        if(t4==0){
            size_t r=(size_t)row_base+row;
            out[r*2+0]=c0+clsb[0];
            out[r*2+1]=c1+clsb[1];
        }
    }
}

// ---------- launch ----------
extern "C" void kernel_launch(void* const* d_in, const int* in_sizes, int n_in,
                              void* d_out, int out_size){
    const float* gimage=(const float*)d_in[0];
    const int*   pts   =(const int*)  d_in[1];
    const float* gn1w=(const float*)d_in[2],  *gn1b=(const float*)d_in[3];
    const float* c1w =(const float*)d_in[4],  *c1b =(const float*)d_in[5];
    const float* gn2w=(const float*)d_in[6],  *gn2b=(const float*)d_in[7];
    const float* c2w =(const float*)d_in[8],  *c2b =(const float*)d_in[9];
    const float* clsw=(const float*)d_in[10], *clsb=(const float*)d_in[11];
    const float* mw1 =(const float*)d_in[12], *mb1 =(const float*)d_in[13];
    const float* mw2 =(const float*)d_in[14], *mb2 =(const float*)d_in[15];
    const float* mw3 =(const float*)d_in[16], *mb3 =(const float*)d_in[17];
    float* out=(float*)d_out;

    cudaFuncSetAttribute(main_kernel, cudaFuncAttributeMaxDynamicSharedMemorySize, SMEM_TOTAL);

    dim3 tgrid(HW/32, CH/32, BS), tblk(32,8);
    transpose_kernel<<<tgrid,tblk>>>(gimage);
    prep_kernel<<<384,256>>>(c1w,c2w,mw1,mw2);
    main_kernel<<<NBLK,256,SMEM_TOTAL>>>(pts,gn1w,gn1b,c1b,gn2w,gn2b,c2b,
                                         clsw,clsb,mb1,mb2,mw3,mb3,out);
}